// round 1
// baseline (speedup 1.0000x reference)
#include <cuda_runtime.h>
#include <math.h>

// ---------------- problem constants ----------------
#define NB   64            // batch
#define SEQT 64            // seq after dropping last frame
#define NT   (NB*SEQT)     // 4096 images
#define CH   128
#define NPIX 49            // 7x7
#define ROWS (NT*NPIX)     // 200704
#define SS   8
#define KK   512
#define EE   64
#define DECAYF 0.99f
#define OMDF   0.010000000707805157f   // float(1.0 - 0.99) as jax computes it
#define EPSF   1e-5f
#define KEPSF  0.00512f                // float(512 * 1e-5)

// ---------------- device scratch (no runtime alloc allowed) ----------------
__device__ float g_bufA[ROWS*CH];      // ~102.8 MB
__device__ float g_bufB[ROWS*CH];      // ~102.8 MB
__device__ float g_part[2*256*CH];     // stats partials (sum, sumsq)
__device__ float g_scale[2][CH];
__device__ float g_shift[2][CH];
__device__ float g_obsfeat[NT*CH];     // (b, t, 128)
__device__ float g_h[NB*64];
__device__ float g_z[NB*SS*EE];
__device__ float g_zq[NB*SS*EE];
__device__ int   g_idx[NB*SS];
__device__ float g_cb[SS*KK*EE];
__device__ float g_ea[SS*KK*EE];
__device__ float g_cs[SS*KK];
__device__ float g_counts[KK];
__device__ float g_sumz[KK*EE];
__device__ float g_gamma[63*NB*CH];
__device__ float g_beta[63*NB*CH];
__device__ float g_dl[2048];
__device__ float g_el[NB*SS];

// ---------------- init: reset all sequential state (every replay) ----------
__global__ void k_init(const float* __restrict__ codebook) {
    int i = blockIdx.x*blockDim.x + threadIdx.x;
    if (i < SS*KK*EE) { float v = codebook[i]; g_cb[i] = v; g_ea[i] = v; }
    if (i < SS*KK)  g_cs[i] = 0.f;
    if (i < NB*64)  g_h[i]  = 0.f;
    if (i < 2048)   g_dl[i] = 0.f;
    if (i < NB*SS)  g_el[i] = 0.f;
}

// ---------------- embedding gather + channel-sum -> g_bufA ------------------
__global__ void k_emb(const int* __restrict__ obs, const float* __restrict__ emb) {
    int n = blockIdx.x;                 // 0..4095  (b*64 + t)
    int b = n >> 6, tt = n & 63;
    int c = threadIdx.x;                // 0..127
    const int base = (b*65 + tt)*147;   // (B,65,3,7,7) int32
    #pragma unroll 7
    for (int p = 0; p < 49; p++) {
        int i0 = obs[base + p];
        int i1 = obs[base + 49 + p] + 147;
        int i2 = obs[base + 98 + p] + 294;
        g_bufA[(n*49 + p)*CH + c] = emb[i0*CH + c] + emb[i1*CH + c] + emb[i2*CH + c];
    }
}

// ---------------- 3x3 SAME conv, 128->128, NHWC ----------------------------
// PASS=1: in g_bufA (raw)            -> out g_bufB
// PASS=2: in g_bufB (BN1+ReLU fused) -> out g_bufA
template<int PASS>
__global__ void __launch_bounds__(64) k_conv(const float* __restrict__ w,
                                             const float* __restrict__ bias) {
    __shared__ float s[81*CH];          // 9x9 zero-padded input tile, 41.5 KB
    const float* in  = (PASS == 1) ? g_bufA : g_bufB;
    float*       out = (PASS == 1) ? g_bufB : g_bufA;
    int n = blockIdx.x;
    int tid = threadIdx.x;              // 0..63

    for (int idx = tid; idx < 81*CH; idx += 64) {
        int p = idx >> 7, c = idx & 127;
        int i = p/9 - 1, j = p%9 - 1;
        float v = 0.f;
        if ((unsigned)i < 7u && (unsigned)j < 7u) {
            v = in[(n*49 + i*7 + j)*CH + c];
            if (PASS == 2) v = fmaxf(v*g_scale[0][c] + g_shift[0][c], 0.f);
        }
        s[idx] = v;
    }
    __syncthreads();

    const int c0 = tid, c1 = tid + 64;
    float a0[49], a1[49];
    float bv0 = bias[c0], bv1 = bias[c1];
    #pragma unroll
    for (int p = 0; p < 49; p++) { a0[p] = bv0; a1[p] = bv1; }

    for (int kk = 0; kk < 9; kk++) {
        int ki = kk/3, kj = kk%3;
        const float*  wp  = w + kk*CH*CH;
        const float4* sp4 = (const float4*)(s + (ki*9 + kj)*CH);
        for (int ci = 0; ci < 128; ci += 4) {
            float w00 = wp[(ci+0)*CH + c0], w01 = wp[(ci+1)*CH + c0];
            float w02 = wp[(ci+2)*CH + c0], w03 = wp[(ci+3)*CH + c0];
            float w10 = wp[(ci+0)*CH + c1], w11 = wp[(ci+1)*CH + c1];
            float w12 = wp[(ci+2)*CH + c1], w13 = wp[(ci+3)*CH + c1];
            int cq = ci >> 2;
            #pragma unroll
            for (int i = 0; i < 7; i++) {
                #pragma unroll
                for (int j = 0; j < 7; j++) {
                    float4 sv = sp4[(i*9 + j)*32 + cq];   // broadcast LDS.128
                    int p = i*7 + j;
                    a0[p] += sv.x*w00; a0[p] += sv.y*w01;
                    a0[p] += sv.z*w02; a0[p] += sv.w*w03;
                    a1[p] += sv.x*w10; a1[p] += sv.y*w11;
                    a1[p] += sv.z*w12; a1[p] += sv.w*w13;
                }
            }
        }
    }
    #pragma unroll
    for (int p = 0; p < 49; p++) {
        out[(n*49 + p)*CH + c0] = a0[p];
        out[(n*49 + p)*CH + c1] = a1[p];
    }
}

// ---------------- batch-norm statistics (two-stage, deterministic) ---------
template<int PASS>
__global__ void k_stats1() {
    const float* x = (PASS == 1) ? g_bufB : g_bufA;
    int blk = blockIdx.x, c = threadIdx.x;      // 256 blocks x 128 threads
    int r0 = blk*784;                           // 200704/256
    float s = 0.f, q = 0.f;
    for (int r = r0; r < r0 + 784; r++) {
        float v = x[r*CH + c];
        s += v; q += v*v;
    }
    g_part[blk*CH + c]          = s;
    g_part[256*CH + blk*CH + c] = q;
}

template<int PASS>
__global__ void k_stats2(const float* __restrict__ gam, const float* __restrict__ bet) {
    int c = threadIdx.x;                        // 128 threads
    float s = 0.f, q = 0.f;
    for (int k = 0; k < 256; k++) {
        s += g_part[k*CH + c];
        q += g_part[256*CH + k*CH + c];
    }
    float m = s / 200704.f;
    float v = q / 200704.f - m*m;
    float istd = 1.f / sqrtf(v + EPSF);
    float sc = gam[c]*istd;
    g_scale[PASS-1][c] = sc;
    g_shift[PASS-1][c] = bet[c] - m*sc;
}

// ---------------- BN2 + ReLU + spatial max-pool -> obs_feat ----------------
__global__ void k_pool() {
    int n = blockIdx.x, c = threadIdx.x;
    float sc = g_scale[1][c], sh = g_shift[1][c];
    float m = 0.f;                              // relu floor
    for (int p = 0; p < 49; p++) {
        float v = fmaxf(g_bufA[(n*49 + p)*CH + c]*sc + sh, 0.f);
        m = fmaxf(m, v);
    }
    g_obsfeat[n*CH + c] = m;
}

// ---------------- per-step: GRU + pre-projection (z) + zero counts ---------
__global__ void k_gru(int t,
                      const float* __restrict__ wih, const float* __restrict__ whh,
                      const float* __restrict__ bih, const float* __restrict__ bhh,
                      const float* __restrict__ pw,  const float* __restrict__ pb) {
    __shared__ float xt[128], hp[64], gi[192], gh[192], hn[64];
    int b = blockIdx.x, tid = threadIdx.x;      // 64 blocks x 192 threads
    if (tid < 128) xt[tid] = g_obsfeat[(b*SEQT + t)*CH + tid];
    if (tid < 64)  hp[tid] = g_h[b*64 + tid];
    // zero this step's counts / sumz (consumed by k_vq, later in stream)
    for (int i = b*192 + tid; i < KK + KK*EE; i += 64*192) {
        if (i < KK) g_counts[i] = 0.f;
        else        g_sumz[i - KK] = 0.f;
    }
    __syncthreads();
    {
        float s1 = bih[tid];
        const float* wr = wih + tid*128;
        #pragma unroll 8
        for (int k = 0; k < 128; k++) s1 += xt[k]*wr[k];
        gi[tid] = s1;
        float s2 = bhh[tid];
        const float* wr2 = whh + tid*64;
        #pragma unroll 8
        for (int k = 0; k < 64; k++) s2 += hp[k]*wr2[k];
        gh[tid] = s2;
    }
    __syncthreads();
    if (tid < 64) {
        float r  = 1.f/(1.f + expf(-(gi[tid]      + gh[tid])));
        float zz = 1.f/(1.f + expf(-(gi[64+tid]   + gh[64+tid])));
        float nn = tanhf(gi[128+tid] + r*gh[128+tid]);
        float h  = (1.f - zz)*nn + zz*hp[tid];
        hn[tid] = h;
        g_h[b*64 + tid] = h;
    }
    __syncthreads();
    for (int j = tid; j < 512; j += 192) {
        float s = pb[j];
        #pragma unroll 8
        for (int k = 0; k < 64; k++) s += hn[k]*pw[k*512 + j];
        g_z[b*512 + j] = s;
    }
}

// ---------------- per-step: VQ argmin + z_q gather (OLD cb) + EMA inputs ---
__global__ void k_vq() {
    __shared__ float zs[64];
    __shared__ float rd[512];
    __shared__ int   ri[512];
    int b = blockIdx.x, s = blockIdx.y, k = threadIdx.x;   // (64,8) x 512
    if (k < 64) zs[k] = g_z[b*512 + s*64 + k];
    __syncthreads();
    const float* cb = g_cb + (s*KK + k)*EE;
    float d = 0.f;
    #pragma unroll 8
    for (int e = 0; e < 64; e++) { float df = zs[e] - cb[e]; d += df*df; }
    rd[k] = d; ri[k] = k;
    __syncthreads();
    for (int st = 256; st > 0; st >>= 1) {
        if (k < st) {
            float dv = rd[k+st]; int iv = ri[k+st];
            if (dv < rd[k] || (dv == rd[k] && iv < ri[k])) { rd[k] = dv; ri[k] = iv; }
        }
        __syncthreads();
    }
    int kmin = ri[0];
    if (k == 0) {
        g_idx[b*SS + s] = kmin;
        g_el[b*SS + s] += rd[0];                 // sum of min-distances (scaled at end)
        atomicAdd(&g_counts[kmin], 1.f);
    }
    if (k < 64) {
        g_zq[(b*SS + s)*EE + k] = g_cb[(s*KK + kmin)*EE + k];   // pre-update cb
        atomicAdd(&g_sumz[kmin*EE + k], zs[k]);
    }
}

// ---------------- per-step: EMA codebook update ----------------------------
__global__ void k_cb() {
    __shared__ float red[512];
    int s = blockIdx.x, k = threadIdx.x;        // 8 blocks x 512 threads
    float cs = g_cs[s*KK + k]*DECAYF + OMDF*g_counts[k];   // counts broadcast over S (ref quirk)
    g_cs[s*KK + k] = cs;
    red[k] = cs;
    __syncthreads();
    for (int st = 256; st > 0; st >>= 1) { if (k < st) red[k] += red[k+st]; __syncthreads(); }
    float ntot = red[0];
    float csn  = (cs + EPSF)/(ntot + KEPSF)*ntot;
    float inv  = 1.f/csn;
    float* ea = g_ea + (s*KK + k)*EE;
    float* cb = g_cb + (s*KK + k)*EE;
    const float* sz = g_sumz + k*EE;
    #pragma unroll 8
    for (int e = 0; e < 64; e++) {
        float v = ea[e]*DECAYF + OMDF*sz[e];
        ea[e] = v;
        cb[e] = v*inv;
    }
}

// ---------------- per-step: FiLM MLP -> gamma/beta (stored per t) ----------
__global__ void k_mlp(int t,
                      const float* __restrict__ w1, const float* __restrict__ b1,
                      const float* __restrict__ w2, const float* __restrict__ b2) {
    __shared__ float zq[512], h1[128];
    int b = blockIdx.x, tid = threadIdx.x;      // 64 blocks x 128 threads
    for (int i = tid; i < 512; i += 128) zq[i] = g_zq[b*512 + i];
    __syncthreads();
    float s = b1[tid];
    #pragma unroll 8
    for (int i = 0; i < 512; i++) s += zq[i]*w1[i*128 + tid];
    h1[tid] = fmaxf(s, 0.f);
    __syncthreads();
    float ga = b2[tid], be = b2[tid + 128];
    #pragma unroll 8
    for (int c = 0; c < 128; c++) {
        float h = h1[c];
        ga += h*w2[c*256 + tid];
        be += h*w2[c*256 + tid + 128];
    }
    g_gamma[(t*NB + b)*CH + tid] = 1.f + ga;
    g_beta [(t*NB + b)*CH + tid] = be;
}

// ---------------- deferred decoder: all masked (t,b,s) rows at once --------
__global__ void __launch_bounds__(128) k_dec(const float* __restrict__ w1, const float* __restrict__ b1,
                                             const float* __restrict__ w2, const float* __restrict__ b2,
                                             const float* __restrict__ w3, const float* __restrict__ b3,
                                             const int*   __restrict__ actions) {
    __shared__ float A[8][128], H[8][128], L[8][6];
    __shared__ float ce_sum;
    int t = blockIdx.x;                         // 0..62
    int b = blockIdx.y;                         // 0..63
    int tid = threadIdx.x;
    if (tid == 0) ce_sum = 0.f;
    float gam = g_gamma[(t*NB + b)*CH + tid];
    float bet = g_beta [(t*NB + b)*CH + tid];
    float bb1 = b1[tid], bb2 = b2[tid];
    __syncthreads();

    for (int s0 = t; s0 <= 62; s0 += 8) {
        int nr = min(8, 63 - s0);
        for (int r = 0; r < nr; r++) {
            float v = g_obsfeat[(b*SEQT + s0 + r)*CH + tid]*gam + bet;
            A[r][tid] = fmaxf(v, 0.f);
        }
        __syncthreads();

        float acc[8];
        #pragma unroll
        for (int r = 0; r < 8; r++) acc[r] = bb1;
        for (int c = 0; c < 128; c++) {
            float wv = w1[c*128 + tid];
            #pragma unroll
            for (int r = 0; r < 8; r++) acc[r] += A[r][c]*wv;
        }
        __syncthreads();
        #pragma unroll
        for (int r = 0; r < 8; r++) H[r][tid] = fmaxf(acc[r], 0.f);
        __syncthreads();

        #pragma unroll
        for (int r = 0; r < 8; r++) acc[r] = bb2;
        for (int c = 0; c < 128; c++) {
            float wv = w2[c*128 + tid];
            #pragma unroll
            for (int r = 0; r < 8; r++) acc[r] += H[r][c]*wv;
        }
        __syncthreads();
        #pragma unroll
        for (int r = 0; r < 8; r++) A[r][tid] = fmaxf(acc[r], 0.f);
        __syncthreads();

        if (tid < 48) {
            int r = tid / 6, j = tid - r*6;
            if (r < nr) {
                float s = b3[j];
                for (int c = 0; c < 128; c++) s += A[r][c]*w3[c*6 + j];
                L[r][j] = s;
            }
        }
        __syncthreads();
        if (tid < nr) {
            int r = tid;
            float mx = L[r][0];
            #pragma unroll
            for (int j = 1; j < 6; j++) mx = fmaxf(mx, L[r][j]);
            float se = 0.f;
            #pragma unroll
            for (int j = 0; j < 6; j++) se += expf(L[r][j] - mx);
            float lse = logf(se) + mx;
            int act = actions[b*63 + (s0 + r)];
            atomicAdd(&ce_sum, lse - L[r][act]);
        }
        __syncthreads();
    }
    if (tid == 0) atomicAdd(&g_dl[(t*NB + b) & 2047], ce_sum);
}

// ---------------- final deterministic reduce -> out[2] ---------------------
__global__ void k_final(float* __restrict__ out) {
    __shared__ float red[256];
    int tid = threadIdx.x;
    float s = 0.f;
    for (int i = tid; i < 2048; i += 256) s += g_dl[i];
    red[tid] = s; __syncthreads();
    for (int st = 128; st > 0; st >>= 1) { if (tid < st) red[tid] += red[tid+st]; __syncthreads(); }
    if (tid == 0) out[0] = red[0] / 64.f;
    __syncthreads();
    float e = 0.f;
    for (int i = tid; i < NB*SS; i += 256) e += g_el[i];
    red[tid] = e; __syncthreads();
    for (int st = 128; st > 0; st >>= 1) { if (tid < st) red[tid] += red[tid+st]; __syncthreads(); }
    if (tid == 0) out[1] = red[0] / (32768.f * 64.f);   // /(B*S*E) then /batch
}

// ---------------- launch --------------------------------------------------
extern "C" void kernel_launch(void* const* d_in, const int* in_sizes, int n_in,
                              void* d_out, int out_size) {
    const int*   obs      = (const int*)  d_in[0];
    const int*   actions  = (const int*)  d_in[1];
    const float* emb      = (const float*)d_in[2];
    const float* conv1_w  = (const float*)d_in[3];
    const float* conv1_b  = (const float*)d_in[4];
    const float* bn1_g    = (const float*)d_in[5];
    const float* bn1_b    = (const float*)d_in[6];
    const float* conv2_w  = (const float*)d_in[7];
    const float* conv2_b  = (const float*)d_in[8];
    const float* bn2_g    = (const float*)d_in[9];
    const float* bn2_b    = (const float*)d_in[10];
    const float* gru_wih  = (const float*)d_in[11];
    const float* gru_whh  = (const float*)d_in[12];
    const float* gru_bih  = (const float*)d_in[13];
    const float* gru_bhh  = (const float*)d_in[14];
    const float* pre_w    = (const float*)d_in[15];
    const float* pre_b    = (const float*)d_in[16];
    const float* codebook = (const float*)d_in[17];
    const float* mlp1_w   = (const float*)d_in[18];
    const float* mlp1_b   = (const float*)d_in[19];
    const float* mlp2_w   = (const float*)d_in[20];
    const float* mlp2_b   = (const float*)d_in[21];
    const float* dec1_w   = (const float*)d_in[22];
    const float* dec1_b   = (const float*)d_in[23];
    const float* dec2_w   = (const float*)d_in[24];
    const float* dec2_b   = (const float*)d_in[25];
    const float* dec3_w   = (const float*)d_in[26];
    const float* dec3_b   = (const float*)d_in[27];
    float* out = (float*)d_out;

    k_init<<<(SS*KK*EE + 255)/256, 256>>>(codebook);
    k_emb<<<NT, 128>>>(obs, emb);
    k_conv<1><<<NT, 64>>>(conv1_w, conv1_b);
    k_stats1<1><<<256, 128>>>();
    k_stats2<1><<<1, 128>>>(bn1_g, bn1_b);
    k_conv<2><<<NT, 64>>>(conv2_w, conv2_b);
    k_stats1<2><<<256, 128>>>();
    k_stats2<2><<<1, 128>>>(bn2_g, bn2_b);
    k_pool<<<NT, 128>>>();

    for (int t = 0; t < 63; t++) {
        k_gru<<<NB, 192>>>(t, gru_wih, gru_whh, gru_bih, gru_bhh, pre_w, pre_b);
        k_vq<<<dim3(NB, SS), 512>>>();
        k_cb<<<SS, 512>>>();
        k_mlp<<<NB, 128>>>(t, mlp1_w, mlp1_b, mlp2_w, mlp2_b);
    }

    k_dec<<<dim3(63, NB), 128>>>(dec1_w, dec1_b, dec2_w, dec2_b, dec3_w, dec3_b, actions);
    k_final<<<1, 256>>>(out);
    (void)in_sizes; (void)n_in; (void)out_size;
}

// round 2
// speedup vs baseline: 1.5108x; 1.5108x over previous
#include <cuda_runtime.h>
#include <math.h>

// ---------------- problem constants ----------------
#define NB   64            // batch
#define SEQT 64            // seq after dropping last frame
#define NT   (NB*SEQT)     // 4096 images
#define CH   128
#define ROWS (NT*49)       // 200704
#define SS   8
#define KK   512
#define EE   64
#define DECAYF 0.99f
#define OMDF   0.010000000707805157f   // float(1.0 - 0.99) as jax computes it
#define EPSF   1e-5f
#define KEPSF  0.00512f                // float(512 * 1e-5)

// ---------------- device scratch (no runtime alloc allowed) ----------------
__device__ float g_bufA[ROWS*CH];      // ~102.8 MB
__device__ float g_bufB[ROWS*CH];      // ~102.8 MB
__device__ float g_part[2*1024*CH];    // stats partials (sum, sumsq)
__device__ float g_scale[2][CH];
__device__ float g_shift[2][CH];
__device__ float g_obsfeat[NT*CH];     // (b, t, 128)
__device__ float g_h[NB*64];
__device__ float g_cb[SS*KK*EE];
__device__ float g_ea[SS*KK*EE];
__device__ float g_cs[SS*KK];
__device__ float g_cnt2[2][KK];        // ping-pong one-hot counts
__device__ float g_sumz2[2][KK*EE];    // ping-pong z-sums
__device__ float g_gamma[63*NB*CH];
__device__ float g_beta[63*NB*CH];
__device__ float g_dl[2048];
__device__ float g_el[NB];

// ---------------- init: reset all sequential state (every replay) ----------
__global__ void k_init(const float* __restrict__ codebook) {
    int i = blockIdx.x*blockDim.x + threadIdx.x;
    if (i < SS*KK*EE) { float v = codebook[i]; g_cb[i] = v; g_ea[i] = v; }
    if (i < SS*KK)  g_cs[i] = 0.f;
    if (i < NB*64)  g_h[i]  = 0.f;
    if (i < 2048)   g_dl[i] = 0.f;
    if (i < NB)     g_el[i] = 0.f;
    if (i < KK)     g_cnt2[0][i] = 0.f;
    if (i < KK*EE)  g_sumz2[0][i] = 0.f;
}

// ---------------- embedding gather + channel-sum -> g_bufA ------------------
__global__ void k_emb(const int* __restrict__ obs, const float* __restrict__ emb) {
    int n = blockIdx.x;                 // 0..4095  (b*64 + t)
    int b = n >> 6, tt = n & 63;
    int c = threadIdx.x;                // 0..127
    const int base = (b*65 + tt)*147;   // (B,65,3,7,7) int32
    #pragma unroll 7
    for (int p = 0; p < 49; p++) {
        int i0 = obs[base + p];
        int i1 = obs[base + 49 + p] + 147;
        int i2 = obs[base + 98 + p] + 294;
        g_bufA[(n*49 + p)*CH + c] = emb[i0*CH + c] + emb[i1*CH + c] + emb[i2*CH + c];
    }
}

// ---------------- 3x3 SAME conv, 128->128, NHWC ----------------------------
// 128 threads/block, one output channel per thread, 49 accumulators.
// PASS=1: in g_bufA (raw)            -> out g_bufB
// PASS=2: in g_bufB (BN1+ReLU fused) -> out g_bufA
template<int PASS>
__global__ void __launch_bounds__(128) k_conv(const float* __restrict__ w,
                                              const float* __restrict__ bias) {
    __shared__ float s[81*CH];          // 9x9 zero-padded input tile, 41.5 KB
    const float* in  = (PASS == 1) ? g_bufA : g_bufB;
    float*       out = (PASS == 1) ? g_bufB : g_bufA;
    int n = blockIdx.x;
    int tid = threadIdx.x;              // 0..127 = cout

    for (int idx = tid; idx < 81*CH; idx += 128) {
        int p = idx >> 7, c = idx & 127;
        int i = p/9 - 1, j = p - (p/9)*9 - 1;
        float v = 0.f;
        if ((unsigned)i < 7u && (unsigned)j < 7u) {
            v = in[(n*49 + i*7 + j)*CH + c];
            if (PASS == 2) v = fmaxf(v*g_scale[0][c] + g_shift[0][c], 0.f);
        }
        s[idx] = v;
    }
    __syncthreads();

    float a[49];
    float bv = bias[tid];
    #pragma unroll
    for (int p = 0; p < 49; p++) a[p] = bv;

    for (int kk = 0; kk < 9; kk++) {
        int ki = kk/3, kj = kk - ki*3;
        const float*  wp  = w + kk*CH*CH + tid;
        const float4* sp4 = (const float4*)(s + (ki*9 + kj)*CH);
        #pragma unroll 4
        for (int ci = 0; ci < 128; ci += 4) {
            float w0 = wp[(ci+0)*CH], w1 = wp[(ci+1)*CH];
            float w2 = wp[(ci+2)*CH], w3 = wp[(ci+3)*CH];
            int cq = ci >> 2;
            #pragma unroll
            for (int i = 0; i < 7; i++) {
                #pragma unroll
                for (int j = 0; j < 7; j++) {
                    float4 sv = sp4[(i*9 + j)*32 + cq];   // broadcast LDS.128
                    int p = i*7 + j;
                    a[p] += sv.x*w0; a[p] += sv.y*w1;
                    a[p] += sv.z*w2; a[p] += sv.w*w3;
                }
            }
        }
    }
    #pragma unroll
    for (int p = 0; p < 49; p++)
        out[(n*49 + p)*CH + tid] = a[p];
}

// ---------------- batch-norm statistics (two-stage, deterministic) ---------
template<int PASS>
__global__ void k_stats1() {
    const float* x = (PASS == 1) ? g_bufB : g_bufA;
    int blk = blockIdx.x, c = threadIdx.x;      // 1024 blocks x 128 threads
    int r0 = blk*196;                           // 200704/1024
    float s = 0.f, q = 0.f;
    for (int r = r0; r < r0 + 196; r++) {
        float v = x[r*CH + c];
        s += v; q += v*v;
    }
    g_part[blk*CH + c]           = s;
    g_part[1024*CH + blk*CH + c] = q;
}

template<int PASS>
__global__ void k_stats2(const float* __restrict__ gam, const float* __restrict__ bet) {
    int c = threadIdx.x;                        // 128 threads
    float s = 0.f, q = 0.f;
    for (int k = 0; k < 1024; k++) {
        s += g_part[k*CH + c];
        q += g_part[1024*CH + k*CH + c];
    }
    float m = s / 200704.f;
    float v = q / 200704.f - m*m;
    float istd = 1.f / sqrtf(v + EPSF);
    float sc = gam[c]*istd;
    g_scale[PASS-1][c] = sc;
    g_shift[PASS-1][c] = bet[c] - m*sc;
}

// ---------------- BN2 + ReLU + spatial max-pool -> obs_feat ----------------
__global__ void k_pool() {
    int n = blockIdx.x, c = threadIdx.x;
    float sc = g_scale[1][c], sh = g_shift[1][c];
    float m = 0.f;                              // relu floor
    #pragma unroll 7
    for (int p = 0; p < 49; p++) {
        float v = fmaxf(g_bufA[(n*49 + p)*CH + c]*sc + sh, 0.f);
        m = fmaxf(m, v);
    }
    g_obsfeat[n*CH + c] = m;
}

// ---------------- fused per-step: GRU + pre-proj + VQ + FiLM-MLP -----------
// one block per batch element b, 512 threads
__global__ void __launch_bounds__(512) k_step(int t,
        const float* __restrict__ wih, const float* __restrict__ whh,
        const float* __restrict__ bih, const float* __restrict__ bhh,
        const float* __restrict__ pw,  const float* __restrict__ pb,
        const float* __restrict__ w1,  const float* __restrict__ b1,
        const float* __restrict__ w2,  const float* __restrict__ b2) {
    __shared__ float xt[128], hp[64], gi[192], gh[192], hv[64];
    __shared__ float z[512], zq[512], h1[128];
    __shared__ float pd[16*8]; __shared__ int pi[16*8];
    __shared__ float mind[8];  __shared__ int kmin[8];
    int b = blockIdx.x, tid = threadIdx.x;
    int par = t & 1;

    if (tid < 128) xt[tid] = g_obsfeat[(b*SEQT + t)*CH + tid];
    if (tid < 64)  hp[tid] = g_h[b*64 + tid];
    __syncthreads();

    if (tid < 192) {
        float s1 = bih[tid];
        const float* wr = wih + tid*128;
        #pragma unroll 8
        for (int k = 0; k < 128; k++) s1 += xt[k]*wr[k];
        gi[tid] = s1;
        float s2 = bhh[tid];
        const float* wr2 = whh + tid*64;
        #pragma unroll 8
        for (int k = 0; k < 64; k++) s2 += hp[k]*wr2[k];
        gh[tid] = s2;
    }
    __syncthreads();
    if (tid < 64) {
        float r  = 1.f/(1.f + expf(-(gi[tid]      + gh[tid])));
        float zz = 1.f/(1.f + expf(-(gi[64+tid]   + gh[64+tid])));
        float nn = tanhf(gi[128+tid] + r*gh[128+tid]);
        float h  = (1.f - zz)*nn + zz*hp[tid];
        hv[tid] = h;
        g_h[b*64 + tid] = h;
    }
    __syncthreads();
    {   // z projection: all 512 threads, 64 MAC each
        float s = pb[tid];
        #pragma unroll 8
        for (int k = 0; k < 64; k++) s += hv[k]*pw[k*512 + tid];
        z[tid] = s;
    }
    __syncthreads();

    // distances: thread tid = code k, all 8 slots
    float dist[8];
    #pragma unroll
    for (int s = 0; s < 8; s++) {
        const float4* cb4 = (const float4*)(g_cb + (s*KK + tid)*EE);
        const float*  zs  = z + s*64;
        float d = 0.f;
        #pragma unroll
        for (int e4 = 0; e4 < 16; e4++) {
            float4 c = cb4[e4];
            float d0 = zs[e4*4+0] - c.x;
            float d1 = zs[e4*4+1] - c.y;
            float d2 = zs[e4*4+2] - c.z;
            float d3 = zs[e4*4+3] - c.w;
            d += d0*d0; d += d1*d1; d += d2*d2; d += d3*d3;
        }
        dist[s] = d;
    }
    int lane = tid & 31, wid = tid >> 5;
    #pragma unroll
    for (int s = 0; s < 8; s++) {
        float d = dist[s]; int ix = tid;
        #pragma unroll
        for (int off = 16; off > 0; off >>= 1) {
            float od = __shfl_down_sync(0xffffffffu, d,  off);
            int   oi = __shfl_down_sync(0xffffffffu, ix, off);
            if (od < d || (od == d && oi < ix)) { d = od; ix = oi; }
        }
        if (lane == 0) { pd[wid*8 + s] = d; pi[wid*8 + s] = ix; }
    }
    __syncthreads();
    if (tid < 8) {
        int s = tid;
        float d = pd[s]; int ix = pi[s];
        for (int w = 1; w < 16; w++) {
            float od = pd[w*8 + s]; int oi = pi[w*8 + s];
            if (od < d || (od == d && oi < ix)) { d = od; ix = oi; }
        }
        mind[s] = d; kmin[s] = ix;
        atomicAdd(&g_cnt2[par][ix], 1.f);
    }
    __syncthreads();
    {   // zq gather (pre-update codebook) + sumz atomics
        int s = tid >> 6, e = tid & 63;
        int km = kmin[s];
        zq[tid] = g_cb[(s*KK + km)*EE + e];
        atomicAdd(&g_sumz2[par][km*EE + e], z[tid]);
    }
    if (tid == 0) {
        float es = 0.f;
        #pragma unroll
        for (int s = 0; s < 8; s++) es += mind[s];
        g_el[b] += es;
    }
    __syncthreads();

    // FiLM MLP
    if (tid < 128) {
        float s = b1[tid];
        #pragma unroll 8
        for (int i = 0; i < 512; i++) s += zq[i]*w1[i*128 + tid];
        h1[tid] = fmaxf(s, 0.f);
    }
    __syncthreads();
    if (tid < 256) {
        float acc = b2[tid];
        #pragma unroll 8
        for (int c = 0; c < 128; c++) acc += h1[c]*w2[c*256 + tid];
        if (tid < 128) g_gamma[(t*NB + b)*CH + tid]       = 1.f + acc;
        else           g_beta [(t*NB + b)*CH + tid - 128] = acc;
    }
}

// ---------------- per-step: EMA codebook update + zero next buffers --------
__global__ void __launch_bounds__(512) k_cbu(int t) {
    __shared__ float red[512];
    int s = blockIdx.x, k = threadIdx.x;        // 8 blocks x 512 threads
    int par = t & 1;
    float cs = g_cs[s*KK + k]*DECAYF + OMDF*g_cnt2[par][k];   // counts broadcast over S (ref quirk)
    g_cs[s*KK + k] = cs;
    red[k] = cs;
    __syncthreads();
    for (int st = 256; st > 0; st >>= 1) { if (k < st) red[k] += red[k+st]; __syncthreads(); }
    float ntot = red[0];
    float csn  = (cs + EPSF)/(ntot + KEPSF)*ntot;
    float inv  = 1.f/csn;
    float4* ea = (float4*)(g_ea + (s*KK + k)*EE);
    float4* cb = (float4*)(g_cb + (s*KK + k)*EE);
    const float4* sz = (const float4*)(g_sumz2[par] + k*EE);
    #pragma unroll
    for (int e = 0; e < 16; e++) {
        float4 a = ea[e], b = sz[e], v;
        v.x = a.x*DECAYF + OMDF*b.x;
        v.y = a.y*DECAYF + OMDF*b.y;
        v.z = a.z*DECAYF + OMDF*b.z;
        v.w = a.w*DECAYF + OMDF*b.w;
        ea[e] = v;
        float4 c; c.x = v.x*inv; c.y = v.y*inv; c.z = v.z*inv; c.w = v.w*inv;
        cb[e] = c;
    }
    // zero the other parity's buffers for the NEXT step
    int np = par ^ 1;
    if (k < 64) g_cnt2[np][s*64 + k] = 0.f;
    for (int i = k; i < 4096; i += 512) g_sumz2[np][s*4096 + i] = 0.f;
}

// ---------------- deferred decoder: all masked (t,b,s) rows at once --------
__global__ void __launch_bounds__(128) k_dec(const float* __restrict__ w1, const float* __restrict__ b1,
                                             const float* __restrict__ w2, const float* __restrict__ b2,
                                             const float* __restrict__ w3, const float* __restrict__ b3,
                                             const int*   __restrict__ actions) {
    __shared__ float A[8][128], H[8][128], L[8][6];
    __shared__ float ce_sum;
    int t = blockIdx.x;                         // 0..62
    int b = blockIdx.y;                         // 0..63
    int tid = threadIdx.x;
    if (tid == 0) ce_sum = 0.f;
    float gam = g_gamma[(t*NB + b)*CH + tid];
    float bet = g_beta [(t*NB + b)*CH + tid];
    float bb1 = b1[tid], bb2 = b2[tid];
    __syncthreads();

    for (int s0 = t; s0 <= 62; s0 += 8) {
        int nr = min(8, 63 - s0);
        for (int r = 0; r < nr; r++) {
            float v = g_obsfeat[(b*SEQT + s0 + r)*CH + tid]*gam + bet;
            A[r][tid] = fmaxf(v, 0.f);
        }
        __syncthreads();

        float acc[8];
        #pragma unroll
        for (int r = 0; r < 8; r++) acc[r] = bb1;
        for (int c = 0; c < 128; c++) {
            float wv = w1[c*128 + tid];
            #pragma unroll
            for (int r = 0; r < 8; r++) acc[r] += A[r][c]*wv;
        }
        __syncthreads();
        #pragma unroll
        for (int r = 0; r < 8; r++) H[r][tid] = fmaxf(acc[r], 0.f);
        __syncthreads();

        #pragma unroll
        for (int r = 0; r < 8; r++) acc[r] = bb2;
        for (int c = 0; c < 128; c++) {
            float wv = w2[c*128 + tid];
            #pragma unroll
            for (int r = 0; r < 8; r++) acc[r] += H[r][c]*wv;
        }
        __syncthreads();
        #pragma unroll
        for (int r = 0; r < 8; r++) A[r][tid] = fmaxf(acc[r], 0.f);
        __syncthreads();

        if (tid < 48) {
            int r = tid / 6, j = tid - r*6;
            if (r < nr) {
                float s = b3[j];
                for (int c = 0; c < 128; c++) s += A[r][c]*w3[c*6 + j];
                L[r][j] = s;
            }
        }
        __syncthreads();
        if (tid < nr) {
            int r = tid;
            float mx = L[r][0];
            #pragma unroll
            for (int j = 1; j < 6; j++) mx = fmaxf(mx, L[r][j]);
            float se = 0.f;
            #pragma unroll
            for (int j = 0; j < 6; j++) se += expf(L[r][j] - mx);
            float lse = logf(se) + mx;
            int act = actions[b*63 + (s0 + r)];
            atomicAdd(&ce_sum, lse - L[r][act]);
        }
        __syncthreads();
    }
    if (tid == 0) atomicAdd(&g_dl[(t*NB + b) & 2047], ce_sum);
}

// ---------------- final deterministic reduce -> out[2] ---------------------
__global__ void k_final(float* __restrict__ out) {
    __shared__ float red[256];
    int tid = threadIdx.x;
    float s = 0.f;
    for (int i = tid; i < 2048; i += 256) s += g_dl[i];
    red[tid] = s; __syncthreads();
    for (int st = 128; st > 0; st >>= 1) { if (tid < st) red[tid] += red[tid+st]; __syncthreads(); }
    if (tid == 0) out[0] = red[0] / 64.f;
    __syncthreads();
    float e = 0.f;
    for (int i = tid; i < NB; i += 256) e += g_el[i];
    red[tid] = e; __syncthreads();
    for (int st = 128; st > 0; st >>= 1) { if (tid < st) red[tid] += red[tid+st]; __syncthreads(); }
    if (tid == 0) out[1] = red[0] / (32768.f * 64.f);   // /(B*S*E) then /batch
}

// ---------------- launch --------------------------------------------------
extern "C" void kernel_launch(void* const* d_in, const int* in_sizes, int n_in,
                              void* d_out, int out_size) {
    const int*   obs      = (const int*)  d_in[0];
    const int*   actions  = (const int*)  d_in[1];
    const float* emb      = (const float*)d_in[2];
    const float* conv1_w  = (const float*)d_in[3];
    const float* conv1_b  = (const float*)d_in[4];
    const float* bn1_g    = (const float*)d_in[5];
    const float* bn1_b    = (const float*)d_in[6];
    const float* conv2_w  = (const float*)d_in[7];
    const float* conv2_b  = (const float*)d_in[8];
    const float* bn2_g    = (const float*)d_in[9];
    const float* bn2_b    = (const float*)d_in[10];
    const float* gru_wih  = (const float*)d_in[11];
    const float* gru_whh  = (const float*)d_in[12];
    const float* gru_bih  = (const float*)d_in[13];
    const float* gru_bhh  = (const float*)d_in[14];
    const float* pre_w    = (const float*)d_in[15];
    const float* pre_b    = (const float*)d_in[16];
    const float* codebook = (const float*)d_in[17];
    const float* mlp1_w   = (const float*)d_in[18];
    const float* mlp1_b   = (const float*)d_in[19];
    const float* mlp2_w   = (const float*)d_in[20];
    const float* mlp2_b   = (const float*)d_in[21];
    const float* dec1_w   = (const float*)d_in[22];
    const float* dec1_b   = (const float*)d_in[23];
    const float* dec2_w   = (const float*)d_in[24];
    const float* dec2_b   = (const float*)d_in[25];
    const float* dec3_w   = (const float*)d_in[26];
    const float* dec3_b   = (const float*)d_in[27];
    float* out = (float*)d_out;

    k_init<<<1024, 256>>>(codebook);
    k_emb<<<NT, 128>>>(obs, emb);
    k_conv<1><<<NT, 128>>>(conv1_w, conv1_b);
    k_stats1<1><<<1024, 128>>>();
    k_stats2<1><<<1, 128>>>(bn1_g, bn1_b);
    k_conv<2><<<NT, 128>>>(conv2_w, conv2_b);
    k_stats1<2><<<1024, 128>>>();
    k_stats2<2><<<1, 128>>>(bn2_g, bn2_b);
    k_pool<<<NT, 128>>>();

    for (int t = 0; t < 63; t++) {
        k_step<<<NB, 512>>>(t, gru_wih, gru_whh, gru_bih, gru_bhh,
                            pre_w, pre_b, mlp1_w, mlp1_b, mlp2_w, mlp2_b);
        k_cbu<<<SS, 512>>>(t);
    }

    k_dec<<<dim3(63, NB), 128>>>(dec1_w, dec1_b, dec2_w, dec2_b, dec3_w, dec3_b, actions);
    k_final<<<1, 256>>>(out);
    (void)in_sizes; (void)n_in; (void)out_size;
}

// round 3
// speedup vs baseline: 2.0861x; 1.3808x over previous
#include <cuda_runtime.h>
#include <math.h>

// ---------------- problem constants ----------------
#define NB   64            // batch
#define SEQT 64            // seq after dropping last frame
#define NT   (NB*SEQT)     // 4096 images
#define CH   128
#define ROWS (NT*49)       // 200704
#define SS   8
#define KK   512
#define EE   64
#define DECAYF 0.99f
#define OMDF   0.010000000707805157f   // float(1.0 - 0.99) as jax computes it
#define EPSF   1e-5f
#define KEPSF  0.00512f                // float(512 * 1e-5)

// ---------------- device scratch (no runtime alloc allowed) ----------------
__device__ float g_bufA[ROWS*CH];      // ~102.8 MB
__device__ float g_bufB[ROWS*CH];      // ~102.8 MB
__device__ float g_part[2*1024*CH];    // stats partials (sum, sumsq)
__device__ float g_scale[2][CH];
__device__ float g_shift[2][CH];
__device__ float g_obsfeat[NT*CH];     // (b, t, 128)
__device__ float g_h[NB*64];
__device__ float g_z[NB*SS*EE];
__device__ float g_zq[NB*SS*EE];
__device__ float g_mind[NB*SS];
__device__ float g_cb[SS*KK*EE];
__device__ float g_ea[SS*KK*EE];
__device__ float g_cs[SS*KK];
__device__ float g_cnt2[2][KK];        // ping-pong one-hot counts
__device__ float g_sumz2[2][KK*EE];    // ping-pong z-sums
__device__ float g_gamma[63*NB*CH];
__device__ float g_beta[63*NB*CH];
__device__ float g_dl[2048];
__device__ float g_el[NB];

// ---------------- packed f32x2 helpers -------------------------------------
__device__ __forceinline__ unsigned long long pk2(float lo, float hi) {
    unsigned long long r;
    asm("mov.b64 %0, {%1,%2};" : "=l"(r) : "f"(lo), "f"(hi));
    return r;
}
__device__ __forceinline__ void fma2(unsigned long long& a, unsigned long long b,
                                     unsigned long long c) {
    asm("fma.rn.f32x2 %0, %1, %2, %0;" : "+l"(a) : "l"(b), "l"(c));
}
__device__ __forceinline__ void unpk2(float& lo, float& hi, unsigned long long v) {
    asm("mov.b64 {%0,%1}, %2;" : "=f"(lo), "=f"(hi) : "l"(v));
}

// ---------------- init: reset all sequential state (every replay) ----------
__global__ void k_init(const float* __restrict__ codebook) {
    int i = blockIdx.x*blockDim.x + threadIdx.x;
    if (i < SS*KK*EE) { float v = codebook[i]; g_cb[i] = v; g_ea[i] = v; }
    if (i < SS*KK)  g_cs[i] = 0.f;
    if (i < NB*64)  g_h[i]  = 0.f;
    if (i < 2048)   g_dl[i] = 0.f;
    if (i < NB)     g_el[i] = 0.f;
    if (i < KK)     g_cnt2[0][i] = 0.f;
    if (i < KK*EE)  g_sumz2[0][i] = 0.f;
}

// tiny filler so that k_conv<1> is the 4th launch (ncu capture slot)
__global__ void k_zero() {
    int i = blockIdx.x*blockDim.x + threadIdx.x;
    if (i < 2048) g_dl[i] = 0.f;
}

// ---------------- embedding gather + channel-sum -> g_bufA ------------------
__global__ void k_emb(const int* __restrict__ obs, const float* __restrict__ emb) {
    int n = blockIdx.x;                 // 0..4095  (b*64 + t)
    int b = n >> 6, tt = n & 63;
    int c = threadIdx.x;                // 0..127
    const int base = (b*65 + tt)*147;   // (B,65,3,7,7) int32
    #pragma unroll 7
    for (int p = 0; p < 49; p++) {
        int i0 = obs[base + p];
        int i1 = obs[base + 49 + p] + 147;
        int i2 = obs[base + 98 + p] + 294;
        g_bufA[(n*49 + p)*CH + c] = emb[i0*CH + c] + emb[i1*CH + c] + emb[i2*CH + c];
    }
}

// ---------------- 3x3 SAME conv, 128->128, NHWC, packed f32x2 --------------
// Channel-major smem tile s2[c][r][x]: r=0..8 covers input rows i=-1..7
// (zero pad), x=0..7 covers input cols j=0..7 (j=7 pad, zero). Channel stride
// 74 floats (even -> LDS.64 aligned; 74 mod 32 = 10 -> only 2-way store bank
// conflicts). Output pixels packed in pairs along j:
//   even accumulator pairs cover outputs (2m, 2m+1)  <- kj=1 taps
//   odd  accumulator pairs cover outputs (2m-1, 2m)  <- kj=0 and kj=2 taps
// Aligned input pairs (o, o+1), o even, feed all three taps; the pads make
// out-of-range taps exact zeros. Final output = even part + odd part.
// PASS=1: in g_bufA (raw)            -> out g_bufB
// PASS=2: in g_bufB (BN1+ReLU fused) -> out g_bufA
template<int PASS>
__global__ void __launch_bounds__(128, 3) k_conv(const float* __restrict__ w,
                                                 const float* __restrict__ bias) {
    __shared__ float s2[128*74];
    const float* in  = (PASS == 1) ? g_bufA : g_bufB;
    float*       out = (PASS == 1) ? g_bufB : g_bufA;
    int n = blockIdx.x;
    int tid = threadIdx.x;              // 0..127 = cout (and channel for tile load)

    // zero own channel region, then fill with data (thread owns channel tid)
    #pragma unroll
    for (int r = 0; r < 74; r++) s2[tid*74 + r] = 0.f;
    {
        float sc = 1.f, sh = 0.f;
        if (PASS == 2) { sc = g_scale[0][tid]; sh = g_shift[0][tid]; }
        #pragma unroll 7
        for (int p = 0; p < 49; p++) {
            int i = p/7, j = p - (p/7)*7;
            float v = in[(n*49 + p)*CH + tid];
            if (PASS == 2) v = fmaxf(v*sc + sh, 0.f);
            s2[tid*74 + (i + 1)*8 + j] = v;
        }
    }
    __syncthreads();

    unsigned long long accE[28], accO[28];
    {
        float bv = bias[tid];
        unsigned long long be = pk2(bv, bv);
        #pragma unroll
        for (int q = 0; q < 28; q++) { accE[q] = be; accO[q] = 0ull; }
    }

    float wn[9];
    {   // preload weights for cin=0
        const float* wp = w + tid;
        #pragma unroll
        for (int kk = 0; kk < 9; kk++) wn[kk] = wp[kk*CH*CH];
    }

    #pragma unroll 1
    for (int cin = 0; cin < 128; cin++) {
        unsigned long long w2[9];
        #pragma unroll
        for (int kk = 0; kk < 9; kk++) w2[kk] = pk2(wn[kk], wn[kk]);
        if (cin < 127) {                // prefetch next cin's weights
            const float* wp = w + (cin + 1)*CH + tid;
            #pragma unroll
            for (int kk = 0; kk < 9; kk++) wn[kk] = wp[kk*CH*CH];
        }
        const unsigned long long* row = (const unsigned long long*)(s2 + cin*74);
        #pragma unroll
        for (int r = 0; r < 9; r++) {
            #pragma unroll
            for (int po = 0; po < 4; po++) {
                unsigned long long P = row[r*4 + po];
                #pragma unroll
                for (int ki = 0; ki < 3; ki++) {
                    int io = r - ki;
                    if (io >= 0 && io <= 6) {
                        fma2(accE[io*4 + po], P, w2[ki*3 + 1]);          // kj=1
                        if (po < 3) fma2(accO[io*4 + po + 1], P, w2[ki*3 + 0]); // kj=0
                        fma2(accO[io*4 + po], P, w2[ki*3 + 2]);          // kj=2
                    }
                }
            }
        }
    }

    // epilogue: recombine even/odd packed halves -> 49 outputs
    #pragma unroll
    for (int io = 0; io < 7; io++) {
        float e_lo[4], e_hi[4], o_lo[4], o_hi[4];
        #pragma unroll
        for (int q = 0; q < 4; q++) {
            unpk2(e_lo[q], e_hi[q], accE[io*4 + q]);
            unpk2(o_lo[q], o_hi[q], accO[io*4 + q]);
        }
        #pragma unroll
        for (int j = 0; j < 7; j++) {
            float ev = (j & 1) ? e_hi[j >> 1] : e_lo[j >> 1];
            float ov = (j & 1) ? o_lo[(j + 1) >> 1] : o_hi[j >> 1];
            out[(n*49 + io*7 + j)*CH + tid] = ev + ov;
        }
    }
}

// ---------------- batch-norm statistics (two-stage, deterministic) ---------
template<int PASS>
__global__ void k_stats1() {
    const float* x = (PASS == 1) ? g_bufB : g_bufA;
    int blk = blockIdx.x, c = threadIdx.x;      // 1024 blocks x 128 threads
    int r0 = blk*196;                           // 200704/1024
    float s = 0.f, q = 0.f;
    for (int r = r0; r < r0 + 196; r++) {
        float v = x[r*CH + c];
        s += v; q += v*v;
    }
    g_part[blk*CH + c]           = s;
    g_part[1024*CH + blk*CH + c] = q;
}

template<int PASS>
__global__ void k_stats2(const float* __restrict__ gam, const float* __restrict__ bet) {
    int c = threadIdx.x;                        // 128 threads
    float s = 0.f, q = 0.f;
    for (int k = 0; k < 1024; k++) {
        s += g_part[k*CH + c];
        q += g_part[1024*CH + k*CH + c];
    }
    float m = s / 200704.f;
    float v = q / 200704.f - m*m;
    float istd = 1.f / sqrtf(v + EPSF);
    float sc = gam[c]*istd;
    g_scale[PASS-1][c] = sc;
    g_shift[PASS-1][c] = bet[c] - m*sc;
}

// ---------------- BN2 + ReLU + spatial max-pool -> obs_feat ----------------
__global__ void k_pool() {
    int n = blockIdx.x, c = threadIdx.x;
    float sc = g_scale[1][c], sh = g_shift[1][c];
    float m = 0.f;                              // relu floor
    #pragma unroll 7
    for (int p = 0; p < 49; p++) {
        float v = fmaxf(g_bufA[(n*49 + p)*CH + c]*sc + sh, 0.f);
        m = fmaxf(m, v);
    }
    g_obsfeat[n*CH + c] = m;
}

// ---------------- per-step A: FiLM MLP of (t-1) + GRU/z of t ---------------
// one block per batch element b, 512 threads.  t runs 0..63:
//   t>0 : MLP using zq(t-1), el += mind(t-1)
//   t<63: GRU step t, write g_z
__global__ void __launch_bounds__(512) k_stepA(int t,
        const float* __restrict__ wih, const float* __restrict__ whh,
        const float* __restrict__ bih, const float* __restrict__ bhh,
        const float* __restrict__ pw,  const float* __restrict__ pb,
        const float* __restrict__ w1,  const float* __restrict__ b1,
        const float* __restrict__ w2,  const float* __restrict__ b2) {
    __shared__ float zq[512], h1[128];
    __shared__ float xt[128], hp[64], gi[192], gh[192], hv[64];
    int b = blockIdx.x, tid = threadIdx.x;

    if (t > 0) {
        zq[tid] = g_zq[b*512 + tid];
        if (tid == 0) {
            float es = 0.f;
            #pragma unroll
            for (int s = 0; s < 8; s++) es += g_mind[b*8 + s];
            g_el[b] += es;
        }
        __syncthreads();
        if (tid < 128) {
            float s = b1[tid];
            #pragma unroll 8
            for (int i = 0; i < 512; i++) s += zq[i]*w1[i*128 + tid];
            h1[tid] = fmaxf(s, 0.f);
        }
        __syncthreads();
        if (tid < 256) {
            float acc = b2[tid];
            #pragma unroll 8
            for (int c = 0; c < 128; c++) acc += h1[c]*w2[c*256 + tid];
            if (tid < 128) g_gamma[((t-1)*NB + b)*CH + tid]       = 1.f + acc;
            else           g_beta [((t-1)*NB + b)*CH + tid - 128] = acc;
        }
    }

    if (t < 63) {
        if (tid < 128) xt[tid] = g_obsfeat[(b*SEQT + t)*CH + tid];
        if (tid < 64)  hp[tid] = g_h[b*64 + tid];
        __syncthreads();
        if (tid < 192) {
            float s1 = bih[tid];
            const float* wr = wih + tid*128;
            #pragma unroll 8
            for (int k = 0; k < 128; k++) s1 += xt[k]*wr[k];
            gi[tid] = s1;
            float s2 = bhh[tid];
            const float* wr2 = whh + tid*64;
            #pragma unroll 8
            for (int k = 0; k < 64; k++) s2 += hp[k]*wr2[k];
            gh[tid] = s2;
        }
        __syncthreads();
        if (tid < 64) {
            float r  = 1.f/(1.f + expf(-(gi[tid]      + gh[tid])));
            float zz = 1.f/(1.f + expf(-(gi[64+tid]   + gh[64+tid])));
            float nn = tanhf(gi[128+tid] + r*gh[128+tid]);
            float h  = (1.f - zz)*nn + zz*hp[tid];
            hv[tid] = h;
            g_h[b*64 + tid] = h;
        }
        __syncthreads();
        {   // z projection: all 512 threads, 64 MAC each
            float s = pb[tid];
            #pragma unroll 8
            for (int k = 0; k < 64; k++) s += hv[k]*pw[k*512 + tid];
            g_z[b*512 + tid] = s;
        }
    }
}

// ---------------- per-step VQ: codebook read ONCE per (slot, bgroup) -------
// grid (8 bgroups, 8 slots) x 512 threads; thread = code k, codes in regs.
__global__ void __launch_bounds__(512) k_vq(int t) {
    __shared__ float zs[8][64];
    __shared__ float pd[16*8]; __shared__ int pi[16*8];
    __shared__ int kminS[8];
    int bg = blockIdx.x, s = blockIdx.y, tid = threadIdx.x;
    int par = t & 1;

    zs[tid >> 6][tid & 63] = g_z[(bg*8 + (tid >> 6))*512 + s*64 + (tid & 63)];
    __syncthreads();

    float4 c4[16];
    {
        const float4* cb4 = (const float4*)(g_cb + (s*KK + tid)*EE);
        #pragma unroll
        for (int e4 = 0; e4 < 16; e4++) c4[e4] = cb4[e4];
    }
    float dist[8];
    #pragma unroll
    for (int lb = 0; lb < 8; lb++) {
        const float* zr = zs[lb];
        float d = 0.f;
        #pragma unroll
        for (int e4 = 0; e4 < 16; e4++) {
            float d0 = zr[e4*4+0] - c4[e4].x;
            float d1 = zr[e4*4+1] - c4[e4].y;
            float d2 = zr[e4*4+2] - c4[e4].z;
            float d3 = zr[e4*4+3] - c4[e4].w;
            d += d0*d0; d += d1*d1; d += d2*d2; d += d3*d3;
        }
        dist[lb] = d;
    }
    int lane = tid & 31, wid = tid >> 5;
    #pragma unroll
    for (int lb = 0; lb < 8; lb++) {
        float d = dist[lb]; int ix = tid;
        #pragma unroll
        for (int off = 16; off > 0; off >>= 1) {
            float od = __shfl_down_sync(0xffffffffu, d,  off);
            int   oi = __shfl_down_sync(0xffffffffu, ix, off);
            if (od < d || (od == d && oi < ix)) { d = od; ix = oi; }
        }
        if (lane == 0) { pd[wid*8 + lb] = d; pi[wid*8 + lb] = ix; }
    }
    __syncthreads();
    if (tid < 8) {
        int lb = tid;
        float d = pd[lb]; int ix = pi[lb];
        #pragma unroll
        for (int w = 1; w < 16; w++) {
            float od = pd[w*8 + lb]; int oi = pi[w*8 + lb];
            if (od < d || (od == d && oi < ix)) { d = od; ix = oi; }
        }
        kminS[lb] = ix;
        g_mind[(bg*8 + lb)*8 + s] = d;
        atomicAdd(&g_cnt2[par][ix], 1.f);
    }
    __syncthreads();
    {
        int lb = tid >> 6, e = tid & 63;
        int km = kminS[lb];
        float zv = zs[lb][e];
        g_zq[((bg*8 + lb)*8 + s)*64 + e] = g_cb[(s*KK + km)*EE + e]; // pre-update cb
        atomicAdd(&g_sumz2[par][km*EE + e], zv);
    }
}

// ---------------- per-step: EMA codebook update + zero next buffers --------
__global__ void __launch_bounds__(512) k_cbu(int t) {
    __shared__ float red[512];
    int s = blockIdx.x, k = threadIdx.x;        // 8 blocks x 512 threads
    int par = t & 1;
    float cs = g_cs[s*KK + k]*DECAYF + OMDF*g_cnt2[par][k];   // counts broadcast over S (ref quirk)
    g_cs[s*KK + k] = cs;
    red[k] = cs;
    __syncthreads();
    for (int st = 256; st > 0; st >>= 1) { if (k < st) red[k] += red[k+st]; __syncthreads(); }
    float ntot = red[0];
    float csn  = (cs + EPSF)/(ntot + KEPSF)*ntot;
    float inv  = 1.f/csn;
    float4* ea = (float4*)(g_ea + (s*KK + k)*EE);
    float4* cb = (float4*)(g_cb + (s*KK + k)*EE);
    const float4* sz = (const float4*)(g_sumz2[par] + k*EE);
    #pragma unroll
    for (int e = 0; e < 16; e++) {
        float4 a = ea[e], b = sz[e], v;
        v.x = a.x*DECAYF + OMDF*b.x;
        v.y = a.y*DECAYF + OMDF*b.y;
        v.z = a.z*DECAYF + OMDF*b.z;
        v.w = a.w*DECAYF + OMDF*b.w;
        ea[e] = v;
        float4 c; c.x = v.x*inv; c.y = v.y*inv; c.z = v.z*inv; c.w = v.w*inv;
        cb[e] = c;
    }
    // zero the other parity's buffers for the NEXT step
    int np = par ^ 1;
    if (k < 64) g_cnt2[np][s*64 + k] = 0.f;
    for (int i = k; i < 4096; i += 512) g_sumz2[np][s*4096 + i] = 0.f;
}

// ---------------- deferred decoder: all masked (t,b,s) rows at once --------
__global__ void __launch_bounds__(128) k_dec(const float* __restrict__ w1, const float* __restrict__ b1,
                                             const float* __restrict__ w2, const float* __restrict__ b2,
                                             const float* __restrict__ w3, const float* __restrict__ b3,
                                             const int*   __restrict__ actions) {
    __shared__ float A[8][128], H[8][128], L[8][6];
    __shared__ float ce_sum;
    int t = blockIdx.x;                         // 0..62
    int b = blockIdx.y;                         // 0..63
    int tid = threadIdx.x;
    if (tid == 0) ce_sum = 0.f;
    float gam = g_gamma[(t*NB + b)*CH + tid];
    float bet = g_beta [(t*NB + b)*CH + tid];
    float bb1 = b1[tid], bb2 = b2[tid];
    __syncthreads();

    for (int s0 = t; s0 <= 62; s0 += 8) {
        int nr = min(8, 63 - s0);
        for (int r = 0; r < nr; r++) {
            float v = g_obsfeat[(b*SEQT + s0 + r)*CH + tid]*gam + bet;
            A[r][tid] = fmaxf(v, 0.f);
        }
        __syncthreads();

        float acc[8];
        #pragma unroll
        for (int r = 0; r < 8; r++) acc[r] = bb1;
        for (int c = 0; c < 128; c++) {
            float wv = w1[c*128 + tid];
            #pragma unroll
            for (int r = 0; r < 8; r++) acc[r] += A[r][c]*wv;
        }
        __syncthreads();
        #pragma unroll
        for (int r = 0; r < 8; r++) H[r][tid] = fmaxf(acc[r], 0.f);
        __syncthreads();

        #pragma unroll
        for (int r = 0; r < 8; r++) acc[r] = bb2;
        for (int c = 0; c < 128; c++) {
            float wv = w2[c*128 + tid];
            #pragma unroll
            for (int r = 0; r < 8; r++) acc[r] += H[r][c]*wv;
        }
        __syncthreads();
        #pragma unroll
        for (int r = 0; r < 8; r++) A[r][tid] = fmaxf(acc[r], 0.f);
        __syncthreads();

        if (tid < 48) {
            int r = tid / 6, j = tid - r*6;
            if (r < nr) {
                float s = b3[j];
                for (int c = 0; c < 128; c++) s += A[r][c]*w3[c*6 + j];
                L[r][j] = s;
            }
        }
        __syncthreads();
        if (tid < nr) {
            int r = tid;
            float mx = L[r][0];
            #pragma unroll
            for (int j = 1; j < 6; j++) mx = fmaxf(mx, L[r][j]);
            float se = 0.f;
            #pragma unroll
            for (int j = 0; j < 6; j++) se += expf(L[r][j] - mx);
            float lse = logf(se) + mx;
            int act = actions[b*63 + (s0 + r)];
            atomicAdd(&ce_sum, lse - L[r][act]);
        }
        __syncthreads();
    }
    if (tid == 0) atomicAdd(&g_dl[(t*NB + b) & 2047], ce_sum);
}

// ---------------- final deterministic reduce -> out[2] ---------------------
__global__ void k_final(float* __restrict__ out) {
    __shared__ float red[256];
    int tid = threadIdx.x;
    float s = 0.f;
    for (int i = tid; i < 2048; i += 256) s += g_dl[i];
    red[tid] = s; __syncthreads();
    for (int st = 128; st > 0; st >>= 1) { if (tid < st) red[tid] += red[tid+st]; __syncthreads(); }
    if (tid == 0) out[0] = red[0] / 64.f;
    __syncthreads();
    float e = 0.f;
    for (int i = tid; i < NB; i += 256) e += g_el[i];
    red[tid] = e; __syncthreads();
    for (int st = 128; st > 0; st >>= 1) { if (tid < st) red[tid] += red[tid+st]; __syncthreads(); }
    if (tid == 0) out[1] = red[0] / (32768.f * 64.f);   // /(B*S*E) then /batch
}

// ---------------- launch --------------------------------------------------
extern "C" void kernel_launch(void* const* d_in, const int* in_sizes, int n_in,
                              void* d_out, int out_size) {
    const int*   obs      = (const int*)  d_in[0];
    const int*   actions  = (const int*)  d_in[1];
    const float* emb      = (const float*)d_in[2];
    const float* conv1_w  = (const float*)d_in[3];
    const float* conv1_b  = (const float*)d_in[4];
    const float* bn1_g    = (const float*)d_in[5];
    const float* bn1_b    = (const float*)d_in[6];
    const float* conv2_w  = (const float*)d_in[7];
    const float* conv2_b  = (const float*)d_in[8];
    const float* bn2_g    = (const float*)d_in[9];
    const float* bn2_b    = (const float*)d_in[10];
    const float* gru_wih  = (const float*)d_in[11];
    const float* gru_whh  = (const float*)d_in[12];
    const float* gru_bih  = (const float*)d_in[13];
    const float* gru_bhh  = (const float*)d_in[14];
    const float* pre_w    = (const float*)d_in[15];
    const float* pre_b    = (const float*)d_in[16];
    const float* codebook = (const float*)d_in[17];
    const float* mlp1_w   = (const float*)d_in[18];
    const float* mlp1_b   = (const float*)d_in[19];
    const float* mlp2_w   = (const float*)d_in[20];
    const float* mlp2_b   = (const float*)d_in[21];
    const float* dec1_w   = (const float*)d_in[22];
    const float* dec1_b   = (const float*)d_in[23];
    const float* dec2_w   = (const float*)d_in[24];
    const float* dec2_b   = (const float*)d_in[25];
    const float* dec3_w   = (const float*)d_in[26];
    const float* dec3_b   = (const float*)d_in[27];
    float* out = (float*)d_out;

    k_init<<<1024, 256>>>(codebook);            // launch 0
    k_emb<<<NT, 128>>>(obs, emb);               // launch 1
    k_zero<<<8, 256>>>();                       // launch 2 (filler for ncu slot)
    k_conv<1><<<NT, 128>>>(conv1_w, conv1_b);   // launch 3 <- ncu capture
    k_stats1<1><<<1024, 128>>>();
    k_stats2<1><<<1, 128>>>(bn1_g, bn1_b);
    k_conv<2><<<NT, 128>>>(conv2_w, conv2_b);
    k_stats1<2><<<1024, 128>>>();
    k_stats2<2><<<1, 128>>>(bn2_g, bn2_b);
    k_pool<<<NT, 128>>>();

    for (int t = 0; t < 63; t++) {
        k_stepA<<<NB, 512>>>(t, gru_wih, gru_whh, gru_bih, gru_bhh,
                             pre_w, pre_b, mlp1_w, mlp1_b, mlp2_w, mlp2_b);
        k_vq<<<dim3(8, 8), 512>>>(t);
        k_cbu<<<SS, 512>>>(t);
    }
    // tail: FiLM MLP for t=62 (+ its el term); GRU branch skipped at t=63
    k_stepA<<<NB, 512>>>(63, gru_wih, gru_whh, gru_bih, gru_bhh,
                         pre_w, pre_b, mlp1_w, mlp1_b, mlp2_w, mlp2_b);

    k_dec<<<dim3(63, NB), 128>>>(dec1_w, dec1_b, dec2_w, dec2_b, dec3_w, dec3_b, actions);
    k_final<<<1, 256>>>(out);
    (void)in_sizes; (void)n_in; (void)out_size;
}